// round 1
// baseline (speedup 1.0000x reference)
#include <cuda_runtime.h>
#include <math.h>

// Problem constants
#define NB    2
#define L     2048
#define DIM   512
#define H     8
#define D     64
#define NH    (NB*H)          // 16
#define ROWS  (NB*L)          // 4096
#define C     64              // chunk length
#define NC    (L/C)           // 32 chunks
#define STSZ  (D*D + D)       // 4160 floats per chunk state (S + s)

// Scratch (device globals; allocation-free)
__device__ float g_q[NH * L * D];          // softplus(q)  [nh][l][d]
__device__ float g_k[NH * L * D];          // softplus(k)
__device__ float g_v[NH * L * D];          // v
__device__ float g_state[NH * NC * STSZ];  // per-chunk states
__device__ float g_prefix[NH * NC * STSZ]; // exclusive prefix states

__device__ __forceinline__ float softplus_f(float x) {
    return (x > 20.0f) ? x : log1pf(__expf(x));
}

// ---------------------------------------------------------------------------
// Kernel 1: Y = X @ W^T with optional softplus, output scattered to
// head-major layout [nh][l][d].
// X: [ROWS][DIM] row-major, W: [DIM][DIM] row-major (Y[r][c] = sum_k X[r][k]W[c][k])
// Block tile 64x64, K-tile 32, 256 threads, 4x4 per thread.
// ---------------------------------------------------------------------------
template <bool SOFTPLUS>
__global__ void gemm_proj(const float* __restrict__ X,
                          const float* __restrict__ W,
                          float* __restrict__ out) {
    __shared__ float Xs[64][33];
    __shared__ float Ws[64][33];

    const int tid = threadIdx.x;
    const int tx = tid & 15;
    const int ty = tid >> 4;
    const int rowBase = blockIdx.y * 64;
    const int colBase = blockIdx.x * 64;

    float acc[4][4];
    #pragma unroll
    for (int r = 0; r < 4; r++)
        #pragma unroll
        for (int c = 0; c < 4; c++) acc[r][c] = 0.0f;

    for (int k0 = 0; k0 < DIM; k0 += 32) {
        #pragma unroll
        for (int i = 0; i < 2; i++) {
            int idx4 = tid + i * 256;        // 0..511 float4 slots
            int r = idx4 >> 3;               // 8 float4 per row of 32
            int c4 = (idx4 & 7) * 4;
            float4 xv = *(const float4*)&X[(rowBase + r) * DIM + k0 + c4];
            Xs[r][c4 + 0] = xv.x; Xs[r][c4 + 1] = xv.y;
            Xs[r][c4 + 2] = xv.z; Xs[r][c4 + 3] = xv.w;
            float4 wv = *(const float4*)&W[(colBase + r) * DIM + k0 + c4];
            Ws[r][c4 + 0] = wv.x; Ws[r][c4 + 1] = wv.y;
            Ws[r][c4 + 2] = wv.z; Ws[r][c4 + 3] = wv.w;
        }
        __syncthreads();

        #pragma unroll
        for (int kk = 0; kk < 32; kk++) {
            float av[4], bv[4];
            #pragma unroll
            for (int r = 0; r < 4; r++) av[r] = Xs[ty * 4 + r][kk];
            #pragma unroll
            for (int c = 0; c < 4; c++) bv[c] = Ws[tx * 4 + c][kk];
            #pragma unroll
            for (int r = 0; r < 4; r++)
                #pragma unroll
                for (int c = 0; c < 4; c++)
                    acc[r][c] += av[r] * bv[c];
        }
        __syncthreads();
    }

    // Epilogue: scatter to [nh][l][d] layout (cols within a thread stay in one head)
    #pragma unroll
    for (int r = 0; r < 4; r++) {
        int row = rowBase + ty * 4 + r;
        int n = row >> 11;                  // row / L
        int l = row & (L - 1);
        int col0 = colBase + tx * 4;
        int h = col0 >> 6;
        int dd = col0 & 63;
        float4 o;
        float v0 = acc[r][0], v1 = acc[r][1], v2 = acc[r][2], v3 = acc[r][3];
        if (SOFTPLUS) {
            v0 = softplus_f(v0); v1 = softplus_f(v1);
            v2 = softplus_f(v2); v3 = softplus_f(v3);
        }
        o.x = v0; o.y = v1; o.z = v2; o.w = v3;
        *(float4*)&out[((n * H + h) * L + l) * D + dd] = o;
    }
}

// ---------------------------------------------------------------------------
// Kernel 2: per-chunk state S_c[dk][dv] = sum_t pk[t][dk]*v[t][dv], s_c[dk]=sum_t pk[t][dk]
// grid (NC, NH), 256 threads.
// ---------------------------------------------------------------------------
__global__ void chunk_state_kernel() {
    __shared__ float pks[64][65];
    __shared__ float vs[64][64];

    const int tid = threadIdx.x;
    const int cc = blockIdx.x;
    const int nh = blockIdx.y;

    const float* kbase = g_k + (nh * L + cc * C) * D;
    const float* vbase = g_v + (nh * L + cc * C) * D;

    #pragma unroll
    for (int i = 0; i < 4; i++) {
        int idx4 = tid + i * 256;           // 1024 float4 = 4096 floats
        int r = idx4 >> 4;
        int c4 = (idx4 & 15) * 4;
        float4 kv = *(const float4*)&kbase[r * D + c4];
        pks[r][c4 + 0] = kv.x; pks[r][c4 + 1] = kv.y;
        pks[r][c4 + 2] = kv.z; pks[r][c4 + 3] = kv.w;
        float4 vv = *(const float4*)&vbase[r * D + c4];
        *(float4*)&vs[r][c4] = vv;
    }
    __syncthreads();

    const int dk = tid >> 2;
    const int dvb = (tid & 3) * 16;
    float acc[16];
    #pragma unroll
    for (int u = 0; u < 16; u++) acc[u] = 0.0f;

    for (int t = 0; t < C; t++) {
        float kvl = pks[t][dk];
        #pragma unroll
        for (int u = 0; u < 4; u++) {
            float4 vv = *(float4*)&vs[t][dvb + u * 4];
            acc[u * 4 + 0] += kvl * vv.x;
            acc[u * 4 + 1] += kvl * vv.y;
            acc[u * 4 + 2] += kvl * vv.z;
            acc[u * 4 + 3] += kvl * vv.w;
        }
    }

    float* sbase = g_state + (nh * NC + cc) * STSZ;
    #pragma unroll
    for (int u = 0; u < 4; u++) {
        float4 o;
        o.x = acc[u * 4 + 0]; o.y = acc[u * 4 + 1];
        o.z = acc[u * 4 + 2]; o.w = acc[u * 4 + 3];
        *(float4*)&sbase[dk * D + dvb + u * 4] = o;
    }

    if (tid < 64) {
        float s = 0.0f;
        for (int t = 0; t < C; t++) s += pks[t][tid];
        sbase[D * D + tid] = s;
    }
}

// ---------------------------------------------------------------------------
// Kernel 3: exclusive prefix scan of chunk states over the chunk axis.
// grid NH, 256 threads; running prefix held in registers (17 per thread).
// ---------------------------------------------------------------------------
__global__ void scan_states_kernel() {
    const int nh = blockIdx.x;
    const int tid = threadIdx.x;
    float run[17];
    #pragma unroll
    for (int j = 0; j < 17; j++) run[j] = 0.0f;

    for (int cc = 0; cc < NC; cc++) {
        const int base = (nh * NC + cc) * STSZ;
        int j = 0;
        for (int idx = tid; idx < STSZ; idx += 256, j++) {
            g_prefix[base + idx] = run[j];
            run[j] += g_state[base + idx];
        }
    }
}

// ---------------------------------------------------------------------------
// Kernel 4: per-chunk output.
//   A = mask(pq @ pk^T);  out = A@v + pq@S_prefix;  den = rowsum(A) + pq.s_prefix
// grid (NC, NH), 256 threads, ~81KB dynamic smem.
// ---------------------------------------------------------------------------
__global__ void attn_out_kernel(float* __restrict__ out) {
    extern __shared__ float sm[];
    float* pqs = sm;                  // 64*65
    float* pks = pqs + 64 * 65;       // 64*65
    float* As  = pks + 64 * 65;       // 64*65
    float* vs  = As + 64 * 65;        // 64*64
    float* Ss  = vs + 64 * 64;        // 64*64
    float* ssm = Ss + 64 * 64;        // 64

    const int tid = threadIdx.x;
    const int cc = blockIdx.x;
    const int nh = blockIdx.y;

    const float* qbase = g_q + (nh * L + cc * C) * D;
    const float* kbase = g_k + (nh * L + cc * C) * D;
    const float* vbase = g_v + (nh * L + cc * C) * D;
    const float* pbase = g_prefix + (nh * NC + cc) * STSZ;

    #pragma unroll
    for (int i = 0; i < 4; i++) {
        int idx4 = tid + i * 256;
        int r = idx4 >> 4;
        int c4 = (idx4 & 15) * 4;
        float4 qv = *(const float4*)&qbase[r * D + c4];
        pqs[r * 65 + c4 + 0] = qv.x; pqs[r * 65 + c4 + 1] = qv.y;
        pqs[r * 65 + c4 + 2] = qv.z; pqs[r * 65 + c4 + 3] = qv.w;
        float4 kv = *(const float4*)&kbase[r * D + c4];
        pks[r * 65 + c4 + 0] = kv.x; pks[r * 65 + c4 + 1] = kv.y;
        pks[r * 65 + c4 + 2] = kv.z; pks[r * 65 + c4 + 3] = kv.w;
        *(float4*)&vs[r * 64 + c4] = *(const float4*)&vbase[r * D + c4];
        *(float4*)&Ss[r * 64 + c4] = *(const float4*)&pbase[r * D + c4];
    }
    if (tid < 64) ssm[tid] = pbase[D * D + tid];
    __syncthreads();

    const int i = tid >> 2;
    const int jb = (tid & 3) * 16;

    // Stage 1: A[i][jb..jb+15]
    float a[16];
    #pragma unroll
    for (int u = 0; u < 16; u++) a[u] = 0.0f;
    for (int d = 0; d < D; d++) {
        float qd = pqs[i * 65 + d];
        #pragma unroll
        for (int u = 0; u < 16; u++)
            a[u] += qd * pks[(jb + u) * 65 + d];
    }
    #pragma unroll
    for (int u = 0; u < 16; u++)
        if (jb + u > i) a[u] = 0.0f;
    #pragma unroll
    for (int u = 0; u < 16; u++)
        As[i * 65 + jb + u] = a[u];
    __syncthreads();

    // Stage 2: out[i][Db..Db+15]
    const int Db = jb;
    float o[16];
    #pragma unroll
    for (int u = 0; u < 16; u++) o[u] = 0.0f;

    for (int j = 0; j <= i; j++) {
        float aij = As[i * 65 + j];
        #pragma unroll
        for (int u = 0; u < 4; u++) {
            float4 vv = *(float4*)&vs[j * 64 + Db + u * 4];
            o[u * 4 + 0] += aij * vv.x;
            o[u * 4 + 1] += aij * vv.y;
            o[u * 4 + 2] += aij * vv.z;
            o[u * 4 + 3] += aij * vv.w;
        }
    }
    for (int d = 0; d < D; d++) {
        float qd = pqs[i * 65 + d];
        #pragma unroll
        for (int u = 0; u < 4; u++) {
            float4 sv = *(float4*)&Ss[d * 64 + Db + u * 4];
            o[u * 4 + 0] += qd * sv.x;
            o[u * 4 + 1] += qd * sv.y;
            o[u * 4 + 2] += qd * sv.z;
            o[u * 4 + 3] += qd * sv.w;
        }
    }

    // Denominator (redundant across the 4 threads of a row; cheap)
    float den = 0.0f;
    for (int j = 0; j <= i; j++) den += As[i * 65 + j];
    for (int d = 0; d < D; d++) den += pqs[i * 65 + d] * ssm[d];
    float inv = 1.0f / den;

    const int n = nh >> 3;
    const int h = nh & 7;
    const int l = cc * C + i;
    float* obase = out + (n * L + l) * DIM + h * D + Db;
    #pragma unroll
    for (int u = 0; u < 4; u++) {
        float4 ov;
        ov.x = o[u * 4 + 0] * inv; ov.y = o[u * 4 + 1] * inv;
        ov.z = o[u * 4 + 2] * inv; ov.w = o[u * 4 + 3] * inv;
        *(float4*)&obase[u * 4] = ov;
    }
}

// ---------------------------------------------------------------------------
extern "C" void kernel_launch(void* const* d_in, const int* in_sizes, int n_in,
                              void* d_out, int out_size) {
    const float* query   = (const float*)d_in[0];
    const float* key_seq = (const float*)d_in[1];
    const float* Wq      = (const float*)d_in[2];
    const float* Wk      = (const float*)d_in[3];
    const float* Wv      = (const float*)d_in[4];
    float* out = (float*)d_out;

    float *gq, *gk, *gv;
    cudaGetSymbolAddress((void**)&gq, g_q);
    cudaGetSymbolAddress((void**)&gk, g_k);
    cudaGetSymbolAddress((void**)&gv, g_v);

    const int SMEM_ATTN = (3 * 64 * 65 + 2 * 64 * 64 + 64) * 4;   // 82944 B
    cudaFuncSetAttribute(attn_out_kernel,
                         cudaFuncAttributeMaxDynamicSharedMemorySize, SMEM_ATTN);

    dim3 ggrid(DIM / 64, ROWS / 64);     // (8, 64)
    gemm_proj<true ><<<ggrid, 256>>>(query,   Wq, gq);
    gemm_proj<true ><<<ggrid, 256>>>(key_seq, Wk, gk);
    gemm_proj<false><<<ggrid, 256>>>(key_seq, Wv, gv);

    chunk_state_kernel<<<dim3(NC, NH), 256>>>();
    scan_states_kernel<<<NH, 256>>>();
    attn_out_kernel<<<dim3(NC, NH), 256, SMEM_ATTN>>>(out);
}

// round 2
// speedup vs baseline: 1.7283x; 1.7283x over previous
#include <cuda_runtime.h>
#include <math.h>

// Problem constants
#define NB    2
#define L     2048
#define DIM   512
#define H     8
#define D     64
#define NH    (NB*H)          // 16
#define ROWS  (NB*L)          // 4096
#define C     64              // chunk length
#define NC    (L/C)           // 32 chunks
#define STSZ  (D*D + D)       // 4160 floats per chunk state (S + s)

// Scratch (device globals; allocation-free)
__device__ float g_q[NH * L * D];          // softplus(q)  [nh][l][d]
__device__ float g_k[NH * L * D];          // softplus(k)
__device__ float g_v[NH * L * D];          // v
__device__ float g_state[NH * NC * STSZ];  // per-chunk states
__device__ float g_prefix[NH * NC * STSZ]; // exclusive prefix states

__device__ __forceinline__ float softplus_f(float x) {
    return (x > 20.0f) ? x : log1pf(__expf(x));
}

// ---------------------------------------------------------------------------
// Kernel 1: Y = X @ W^T (+softplus), scattered to head-major [nh][l][d].
// Block tile M=128, N=64, K-tile=32. 256 threads, 8x4 per thread.
// Smem held k-major so operand fetches are LDS.128.
// ---------------------------------------------------------------------------
template <bool SOFTPLUS>
__global__ void gemm_proj(const float* __restrict__ X,
                          const float* __restrict__ W,
                          float* __restrict__ out) {
    __shared__ float XsT[32][132];   // [k][m]
    __shared__ float WsT[32][68];    // [k][n]

    const int tid = threadIdx.x;
    const int tx = tid & 15;         // n block: tx*4
    const int ty = tid >> 4;         // m block: ty*8
    const int rowBase = blockIdx.y * 128;
    const int colBase = blockIdx.x * 64;

    const float* Xg = X + rowBase * DIM;
    const float* Wg = W + colBase * DIM;

    float4 xl[4], wl[2];

    // prefetch first K-tile into registers
    #pragma unroll
    for (int i = 0; i < 4; i++) {
        int q = tid + i * 256;                       // 1024 float4 of X tile
        xl[i] = *(const float4*)&Xg[(q >> 3) * DIM + (q & 7) * 4];
    }
    #pragma unroll
    for (int i = 0; i < 2; i++) {
        int q = tid + i * 256;                       // 512 float4 of W tile
        wl[i] = *(const float4*)&Wg[(q >> 3) * DIM + (q & 7) * 4];
    }

    float acc[8][4];
    #pragma unroll
    for (int r = 0; r < 8; r++)
        #pragma unroll
        for (int c = 0; c < 4; c++) acc[r][c] = 0.0f;

    for (int k0 = 0; k0 < DIM; k0 += 32) {
        // spill prefetched tile to smem, transposed to k-major
        #pragma unroll
        for (int i = 0; i < 4; i++) {
            int q = tid + i * 256;
            int r = q >> 3, kq = (q & 7) * 4;
            XsT[kq + 0][r] = xl[i].x; XsT[kq + 1][r] = xl[i].y;
            XsT[kq + 2][r] = xl[i].z; XsT[kq + 3][r] = xl[i].w;
        }
        #pragma unroll
        for (int i = 0; i < 2; i++) {
            int q = tid + i * 256;
            int r = q >> 3, kq = (q & 7) * 4;
            WsT[kq + 0][r] = wl[i].x; WsT[kq + 1][r] = wl[i].y;
            WsT[kq + 2][r] = wl[i].z; WsT[kq + 3][r] = wl[i].w;
        }
        __syncthreads();

        // prefetch next K-tile
        if (k0 + 32 < DIM) {
            #pragma unroll
            for (int i = 0; i < 4; i++) {
                int q = tid + i * 256;
                xl[i] = *(const float4*)&Xg[(q >> 3) * DIM + k0 + 32 + (q & 7) * 4];
            }
            #pragma unroll
            for (int i = 0; i < 2; i++) {
                int q = tid + i * 256;
                wl[i] = *(const float4*)&Wg[(q >> 3) * DIM + k0 + 32 + (q & 7) * 4];
            }
        }

        #pragma unroll
        for (int kk = 0; kk < 32; kk++) {
            float4 a0 = *(float4*)&XsT[kk][ty * 8];
            float4 a1 = *(float4*)&XsT[kk][ty * 8 + 4];
            float4 b  = *(float4*)&WsT[kk][tx * 4];
            float am[8] = {a0.x, a0.y, a0.z, a0.w, a1.x, a1.y, a1.z, a1.w};
            float bn[4] = {b.x, b.y, b.z, b.w};
            #pragma unroll
            for (int r = 0; r < 8; r++)
                #pragma unroll
                for (int c = 0; c < 4; c++)
                    acc[r][c] += am[r] * bn[c];
        }
        __syncthreads();
    }

    // epilogue: optional softplus, scatter to [nh][l][d]
    const int col0 = colBase + tx * 4;
    const int h = col0 >> 6;
    const int dd = col0 & 63;
    #pragma unroll
    for (int r = 0; r < 8; r++) {
        int row = rowBase + ty * 8 + r;
        int n = row >> 11;
        int l = row & (L - 1);
        float v0 = acc[r][0], v1 = acc[r][1], v2 = acc[r][2], v3 = acc[r][3];
        if (SOFTPLUS) {
            v0 = softplus_f(v0); v1 = softplus_f(v1);
            v2 = softplus_f(v2); v3 = softplus_f(v3);
        }
        float4 o; o.x = v0; o.y = v1; o.z = v2; o.w = v3;
        *(float4*)&out[((n * H + h) * L + l) * D + dd] = o;
    }
}

// ---------------------------------------------------------------------------
// Kernel 2: per-chunk state S[dk][dv] = sum_t pk[t][dk]*v[t][dv]; s[dk]=sum_t pk[t][dk]
// grid (NC, NH), 256 threads, 4x4 register tile per thread.
// ---------------------------------------------------------------------------
__global__ void chunk_state_kernel() {
    __shared__ float pks[64][68];   // [t][dk]
    __shared__ float vs[64][68];    // [t][dv]

    const int tid = threadIdx.x;
    const int cc = blockIdx.x;
    const int nh = blockIdx.y;

    const float* kbase = g_k + (nh * L + cc * C) * D;
    const float* vbase = g_v + (nh * L + cc * C) * D;

    #pragma unroll
    for (int i = 0; i < 4; i++) {
        int q4 = tid + i * 256;
        int r = q4 >> 4;
        int c4 = (q4 & 15) * 4;
        *(float4*)&pks[r][c4] = *(const float4*)&kbase[r * D + c4];
        *(float4*)&vs[r][c4]  = *(const float4*)&vbase[r * D + c4];
    }
    __syncthreads();

    const int dk0 = (tid >> 4) * 4;
    const int dv0 = (tid & 15) * 4;
    float acc[4][4];
    #pragma unroll
    for (int r = 0; r < 4; r++)
        #pragma unroll
        for (int c = 0; c < 4; c++) acc[r][c] = 0.0f;

    #pragma unroll 8
    for (int t = 0; t < C; t++) {
        float4 a = *(float4*)&pks[t][dk0];
        float4 b = *(float4*)&vs[t][dv0];
        float am[4] = {a.x, a.y, a.z, a.w};
        float bn[4] = {b.x, b.y, b.z, b.w};
        #pragma unroll
        for (int r = 0; r < 4; r++)
            #pragma unroll
            for (int c = 0; c < 4; c++)
                acc[r][c] += am[r] * bn[c];
    }

    float* sbase = g_state + (nh * NC + cc) * STSZ;
    #pragma unroll
    for (int r = 0; r < 4; r++) {
        float4 o;
        o.x = acc[r][0]; o.y = acc[r][1]; o.z = acc[r][2]; o.w = acc[r][3];
        *(float4*)&sbase[(dk0 + r) * D + dv0] = o;
    }

    if (tid < 64) {
        float s = 0.0f;
        #pragma unroll 8
        for (int t = 0; t < C; t++) s += pks[t][tid];
        sbase[D * D + tid] = s;
    }
}

// ---------------------------------------------------------------------------
// Kernel 3: exclusive prefix scan over chunks, parallel over state slices.
// grid (NH, 17), 256 threads; each thread owns one state element.
// ---------------------------------------------------------------------------
__global__ void scan_states_kernel() {
    const int nh = blockIdx.x;
    const int idx = blockIdx.y * 256 + threadIdx.x;
    if (idx >= STSZ) return;
    float run = 0.0f;
    int base = nh * NC * STSZ + idx;
    #pragma unroll 4
    for (int cc = 0; cc < NC; cc++) {
        g_prefix[base] = run;
        run += g_state[base];
        base += STSZ;
    }
}

// ---------------------------------------------------------------------------
// Kernel 4: per-chunk output, 4x4 register tiles, k-major smem.
//   A = mask(pq @ pk^T);  out = (A@v + pq@S_prefix) / (rowsum(A)+pq.s_prefix)
// ---------------------------------------------------------------------------
__global__ void attn_out_kernel(float* __restrict__ out) {
    extern __shared__ float sm[];
    float* pqT = sm;                  // [d][i]  64*68
    float* pkT = pqT + 64 * 68;       // [d][j]  64*68
    float* AsT = pkT + 64 * 68;       // [j][i]  64*68
    float* vs  = AsT + 64 * 68;       // [t][dv] 64*68
    float* Ss  = vs  + 64 * 68;       // [d][dv] 64*68
    float* ssm = Ss  + 64 * 68;       // 64
    float* dinv= ssm + 64;            // 64

    const int tid = threadIdx.x;
    const int cc = blockIdx.x;
    const int nh = blockIdx.y;

    const float* qbase = g_q + (nh * L + cc * C) * D;
    const float* kbase = g_k + (nh * L + cc * C) * D;
    const float* vbase = g_v + (nh * L + cc * C) * D;
    const float* pbase = g_prefix + (nh * NC + cc) * STSZ;

    #pragma unroll
    for (int i = 0; i < 4; i++) {
        int q4 = tid + i * 256;
        int r = q4 >> 4;
        int c4 = (q4 & 15) * 4;
        float4 qv = *(const float4*)&qbase[r * D + c4];
        pqT[(c4 + 0) * 68 + r] = qv.x; pqT[(c4 + 1) * 68 + r] = qv.y;
        pqT[(c4 + 2) * 68 + r] = qv.z; pqT[(c4 + 3) * 68 + r] = qv.w;
        float4 kv = *(const float4*)&kbase[r * D + c4];
        pkT[(c4 + 0) * 68 + r] = kv.x; pkT[(c4 + 1) * 68 + r] = kv.y;
        pkT[(c4 + 2) * 68 + r] = kv.z; pkT[(c4 + 3) * 68 + r] = kv.w;
        *(float4*)&vs[r * 68 + c4] = *(const float4*)&vbase[r * D + c4];
        *(float4*)&Ss[r * 68 + c4] = *(const float4*)&pbase[r * D + c4];
    }
    if (tid < 64) ssm[tid] = pbase[D * D + tid];
    __syncthreads();

    const int i0 = (tid >> 4) * 4;
    const int j0 = (tid & 15) * 4;

    // Stage 1: A tile (4x4 per thread)
    float a[4][4];
    #pragma unroll
    for (int r = 0; r < 4; r++)
        #pragma unroll
        for (int c = 0; c < 4; c++) a[r][c] = 0.0f;

    #pragma unroll 8
    for (int d = 0; d < D; d++) {
        float4 qa = *(float4*)&pqT[d * 68 + i0];
        float4 kb = *(float4*)&pkT[d * 68 + j0];
        float am[4] = {qa.x, qa.y, qa.z, qa.w};
        float bn[4] = {kb.x, kb.y, kb.z, kb.w};
        #pragma unroll
        for (int r = 0; r < 4; r++)
            #pragma unroll
            for (int c = 0; c < 4; c++)
                a[r][c] += am[r] * bn[c];
    }
    // mask and store transposed
    #pragma unroll
    for (int r = 0; r < 4; r++)
        #pragma unroll
        for (int c = 0; c < 4; c++) {
            int i = i0 + r, j = j0 + c;
            AsT[j * 68 + i] = (j <= i) ? a[r][c] : 0.0f;
        }
    __syncthreads();

    // Denominator per row
    if (tid < 64) {
        float den = 0.0f;
        #pragma unroll 8
        for (int j = 0; j < C; j++) den += AsT[j * 68 + tid];
        #pragma unroll 8
        for (int d = 0; d < D; d++) den += pqT[d * 68 + tid] * ssm[d];
        dinv[tid] = 1.0f / den;
    }
    __syncthreads();

    // Stage 2: out tile = A@v + q@S  (4x4 per thread; dv block = j0)
    float o[4][4];
    #pragma unroll
    for (int r = 0; r < 4; r++)
        #pragma unroll
        for (int c = 0; c < 4; c++) o[r][c] = 0.0f;

    #pragma unroll 8
    for (int j = 0; j < C; j++) {
        float4 aa = *(float4*)&AsT[j * 68 + i0];
        float4 vv = *(float4*)&vs[j * 68 + j0];
        float am[4] = {aa.x, aa.y, aa.z, aa.w};
        float bn[4] = {vv.x, vv.y, vv.z, vv.w};
        #pragma unroll
        for (int r = 0; r < 4; r++)
            #pragma unroll
            for (int c = 0; c < 4; c++)
                o[r][c] += am[r] * bn[c];
    }
    #pragma unroll 8
    for (int d = 0; d < D; d++) {
        float4 qa = *(float4*)&pqT[d * 68 + i0];
        float4 sv = *(float4*)&Ss[d * 68 + j0];
        float am[4] = {qa.x, qa.y, qa.z, qa.w};
        float bn[4] = {sv.x, sv.y, sv.z, sv.w};
        #pragma unroll
        for (int r = 0; r < 4; r++)
            #pragma unroll
            for (int c = 0; c < 4; c++)
                o[r][c] += am[r] * bn[c];
    }

    const int n = nh >> 3;
    const int h = nh & 7;
    #pragma unroll
    for (int r = 0; r < 4; r++) {
        int i = i0 + r;
        float inv = dinv[i];
        int l = cc * C + i;
        float4 ov;
        ov.x = o[r][0] * inv; ov.y = o[r][1] * inv;
        ov.z = o[r][2] * inv; ov.w = o[r][3] * inv;
        *(float4*)&out[(n * L + l) * DIM + h * D + j0] = ov;
    }
}

// ---------------------------------------------------------------------------
extern "C" void kernel_launch(void* const* d_in, const int* in_sizes, int n_in,
                              void* d_out, int out_size) {
    const float* query   = (const float*)d_in[0];
    const float* key_seq = (const float*)d_in[1];
    const float* Wq      = (const float*)d_in[2];
    const float* Wk      = (const float*)d_in[3];
    const float* Wv      = (const float*)d_in[4];
    float* out = (float*)d_out;

    float *gq, *gk, *gv;
    cudaGetSymbolAddress((void**)&gq, g_q);
    cudaGetSymbolAddress((void**)&gk, g_k);
    cudaGetSymbolAddress((void**)&gv, g_v);

    const int SMEM_ATTN = (5 * 64 * 68 + 128) * 4;   // 87552 B
    cudaFuncSetAttribute(attn_out_kernel,
                         cudaFuncAttributeMaxDynamicSharedMemorySize, SMEM_ATTN);

    dim3 ggrid(DIM / 64, ROWS / 128);    // (8, 32)
    gemm_proj<true ><<<ggrid, 256>>>(query,   Wq, gq);
    gemm_proj<true ><<<ggrid, 256>>>(key_seq, Wk, gk);
    gemm_proj<false><<<ggrid, 256>>>(key_seq, Wv, gv);

    chunk_state_kernel<<<dim3(NC, NH), 256>>>();
    scan_states_kernel<<<dim3(NH, (STSZ + 255) / 256), 256>>>();
    attn_out_kernel<<<dim3(NC, NH), 256, SMEM_ATTN>>>(out);
}

// round 3
// speedup vs baseline: 2.7780x; 1.6074x over previous
#include <cuda_runtime.h>
#include <math.h>

// Problem constants
#define NB    2
#define L     2048
#define DIM   512
#define H     8
#define D     64
#define NH    (NB*H)          // 16
#define ROWS  (NB*L)          // 4096
#define C     64              // chunk length
#define NC    (L/C)           // 32 chunks
#define STSZ  (D*D + D)       // 4160 floats per chunk state (S + s)

// Scratch (device globals; allocation-free)
__device__ float g_q[NH * L * D];          // softplus(q)  [nh][l][d]
__device__ float g_k[NH * L * D];          // softplus(k)
__device__ float g_v[NH * L * D];          // v
__device__ float g_state[NH * NC * STSZ];  // per-chunk states
__device__ float g_prefix[NH * NC * STSZ]; // exclusive prefix states

__device__ __forceinline__ float softplus_f(float x) {
    return (x > 20.0f) ? x : log1pf(__expf(x));
}

__device__ __forceinline__ unsigned cvt_tf32(float x) {
    unsigned u;
    asm("cvt.rna.tf32.f32 %0, %1;" : "=r"(u) : "f"(x));
    return u;
}

// ---------------------------------------------------------------------------
// Kernel 1: tensor-core TF32 GEMM. Y = X @ W^T (+softplus), scattered to
// head-major [nh][l][d].
// Block tile 128x128, K-tile 32, 256 threads (8 warps), warp tile 64x32.
// Smem holds tf32 operands in mma-fragment-permuted layout so fragment
// fetches are LDS.128 (A) / LDS.64 (B).
// ---------------------------------------------------------------------------
template <bool SOFTPLUS>
__global__ void __launch_bounds__(256, 1)
gemm_proj_tc(const float* __restrict__ X,
             const float* __restrict__ W,
             float* __restrict__ out) {
    // As[kf][mf][lane][reg]  (4*8*32*4 = 4096 u32 = 16KB)
    // Bs[kf][nf][lane][reg]  (4*16*32*2 = 4096 u32 = 16KB)
    __shared__ unsigned As[4][8][32][4];
    __shared__ unsigned Bs[4][16][32][2];

    const int tid  = threadIdx.x;
    const int lane = tid & 31;
    const int warp = tid >> 5;
    const int wm = warp >> 2;          // 0..1  (64-row slab)
    const int wn = warp & 3;           // 0..3  (32-col slab)
    const int g  = lane >> 2;          // groupID
    const int tg = lane & 3;           // thread-in-group

    const int rowBase = blockIdx.y * 128;
    const int colBase = blockIdx.x * 128;

    const float* Xg = X + rowBase * DIM;
    const float* Wg = W + colBase * DIM;

    // per-thread staging coords: q = tid + i*256; row = q>>3, k4 = (q&7)*4
    float4 xl[4], wl[4];
    #pragma unroll
    for (int i = 0; i < 4; i++) {
        int q = tid + i * 256;
        xl[i] = *(const float4*)&Xg[(q >> 3) * DIM + (q & 7) * 4];
        wl[i] = *(const float4*)&Wg[(q >> 3) * DIM + (q & 7) * 4];
    }

    float acc[4][4][4];                // [mf][nf][reg]
    #pragma unroll
    for (int a = 0; a < 4; a++)
        #pragma unroll
        for (int b = 0; b < 4; b++)
            #pragma unroll
            for (int r = 0; r < 4; r++) acc[a][b][r] = 0.0f;

    for (int k0 = 0; k0 < DIM; k0 += 32) {
        // ---- stage prefetched tile into permuted smem (with tf32 cvt) ----
        #pragma unroll
        for (int i = 0; i < 4; i++) {
            int q  = tid + i * 256;
            int r  = q >> 3;            // 0..127
            int k4 = (q & 7) * 4;       // 0,4,...,28
            int kf   = k4 >> 3;
            int hi_k = (k4 >> 2) & 1;
            // A element (m=r, k=k4+e): lane=gA*4+e, reg=hi_k*2+hi_m
            int mf   = r >> 4;
            int mr   = r & 15;
            int gA   = mr & 7;
            int regA = hi_k * 2 + (mr >> 3);
            As[kf][mf][gA * 4 + 0][regA] = cvt_tf32(xl[i].x);
            As[kf][mf][gA * 4 + 1][regA] = cvt_tf32(xl[i].y);
            As[kf][mf][gA * 4 + 2][regA] = cvt_tf32(xl[i].z);
            As[kf][mf][gA * 4 + 3][regA] = cvt_tf32(xl[i].w);
            // B element (n=r, k=k4+e): lane=gB*4+e, reg=hi_k
            int nf = r >> 3;
            int gB = r & 7;
            Bs[kf][nf][gB * 4 + 0][hi_k] = cvt_tf32(wl[i].x);
            Bs[kf][nf][gB * 4 + 1][hi_k] = cvt_tf32(wl[i].y);
            Bs[kf][nf][gB * 4 + 2][hi_k] = cvt_tf32(wl[i].z);
            Bs[kf][nf][gB * 4 + 3][hi_k] = cvt_tf32(wl[i].w);
        }
        __syncthreads();

        // ---- prefetch next K-tile ----
        if (k0 + 32 < DIM) {
            #pragma unroll
            for (int i = 0; i < 4; i++) {
                int q = tid + i * 256;
                xl[i] = *(const float4*)&Xg[(q >> 3) * DIM + k0 + 32 + (q & 7) * 4];
                wl[i] = *(const float4*)&Wg[(q >> 3) * DIM + k0 + 32 + (q & 7) * 4];
            }
        }

        // ---- compute: 4 k-steps of m16n8k8 ----
        #pragma unroll
        for (int kf = 0; kf < 4; kf++) {
            unsigned afr[4][4], bfr[4][2];
            #pragma unroll
            for (int mf = 0; mf < 4; mf++) {
                uint4 v = *(uint4*)&As[kf][wm * 4 + mf][lane][0];
                afr[mf][0] = v.x; afr[mf][1] = v.y; afr[mf][2] = v.z; afr[mf][3] = v.w;
            }
            #pragma unroll
            for (int nf = 0; nf < 4; nf++) {
                uint2 v = *(uint2*)&Bs[kf][wn * 4 + nf][lane][0];
                bfr[nf][0] = v.x; bfr[nf][1] = v.y;
            }
            #pragma unroll
            for (int mf = 0; mf < 4; mf++)
                #pragma unroll
                for (int nf = 0; nf < 4; nf++) {
                    asm volatile(
                        "mma.sync.aligned.m16n8k8.row.col.f32.tf32.tf32.f32 "
                        "{%0,%1,%2,%3}, {%4,%5,%6,%7}, {%8,%9}, {%0,%1,%2,%3};"
                        : "+f"(acc[mf][nf][0]), "+f"(acc[mf][nf][1]),
                          "+f"(acc[mf][nf][2]), "+f"(acc[mf][nf][3])
                        : "r"(afr[mf][0]), "r"(afr[mf][1]),
                          "r"(afr[mf][2]), "r"(afr[mf][3]),
                          "r"(bfr[nf][0]), "r"(bfr[nf][1]));
                }
        }
        __syncthreads();
    }

    // ---- epilogue: softplus + scatter to [nh][l][d] ----
    #pragma unroll
    for (int mf = 0; mf < 4; mf++) {
        #pragma unroll
        for (int nf = 0; nf < 4; nf++) {
            int col = colBase + wn * 32 + nf * 8 + tg * 2;
            int h = col >> 6;
            int dd = col & 63;
            #pragma unroll
            for (int half = 0; half < 2; half++) {
                int row = rowBase + wm * 64 + mf * 16 + half * 8 + g;
                int n = row >> 11;
                int l = row & (L - 1);
                float v0 = acc[mf][nf][half * 2 + 0];
                float v1 = acc[mf][nf][half * 2 + 1];
                if (SOFTPLUS) { v0 = softplus_f(v0); v1 = softplus_f(v1); }
                float2 o; o.x = v0; o.y = v1;
                *(float2*)&out[((n * H + h) * L + l) * D + dd] = o;
            }
        }
    }
}

// ---------------------------------------------------------------------------
// Kernel 2: per-chunk state S[dk][dv] = sum_t pk[t][dk]*v[t][dv]; s[dk]=sum_t pk[t][dk]
// ---------------------------------------------------------------------------
__global__ void chunk_state_kernel() {
    __shared__ float pks[64][68];   // [t][dk]
    __shared__ float vs[64][68];    // [t][dv]

    const int tid = threadIdx.x;
    const int cc = blockIdx.x;
    const int nh = blockIdx.y;

    const float* kbase = g_k + (nh * L + cc * C) * D;
    const float* vbase = g_v + (nh * L + cc * C) * D;

    #pragma unroll
    for (int i = 0; i < 4; i++) {
        int q4 = tid + i * 256;
        int r = q4 >> 4;
        int c4 = (q4 & 15) * 4;
        *(float4*)&pks[r][c4] = *(const float4*)&kbase[r * D + c4];
        *(float4*)&vs[r][c4]  = *(const float4*)&vbase[r * D + c4];
    }
    __syncthreads();

    const int dk0 = (tid >> 4) * 4;
    const int dv0 = (tid & 15) * 4;
    float acc[4][4];
    #pragma unroll
    for (int r = 0; r < 4; r++)
        #pragma unroll
        for (int c = 0; c < 4; c++) acc[r][c] = 0.0f;

    #pragma unroll 8
    for (int t = 0; t < C; t++) {
        float4 a = *(float4*)&pks[t][dk0];
        float4 b = *(float4*)&vs[t][dv0];
        float am[4] = {a.x, a.y, a.z, a.w};
        float bn[4] = {b.x, b.y, b.z, b.w};
        #pragma unroll
        for (int r = 0; r < 4; r++)
            #pragma unroll
            for (int c = 0; c < 4; c++)
                acc[r][c] += am[r] * bn[c];
    }

    float* sbase = g_state + (nh * NC + cc) * STSZ;
    #pragma unroll
    for (int r = 0; r < 4; r++) {
        float4 o;
        o.x = acc[r][0]; o.y = acc[r][1]; o.z = acc[r][2]; o.w = acc[r][3];
        *(float4*)&sbase[(dk0 + r) * D + dv0] = o;
    }

    if (tid < 64) {
        float s = 0.0f;
        #pragma unroll 8
        for (int t = 0; t < C; t++) s += pks[t][tid];
        sbase[D * D + tid] = s;
    }
}

// ---------------------------------------------------------------------------
// Kernel 3: exclusive prefix scan over chunks, parallel over state slices.
// ---------------------------------------------------------------------------
__global__ void scan_states_kernel() {
    const int nh = blockIdx.x;
    const int idx = blockIdx.y * 256 + threadIdx.x;
    if (idx >= STSZ) return;
    float run = 0.0f;
    int base = nh * NC * STSZ + idx;
    #pragma unroll 4
    for (int cc = 0; cc < NC; cc++) {
        g_prefix[base] = run;
        run += g_state[base];
        base += STSZ;
    }
}

// ---------------------------------------------------------------------------
// Kernel 4: per-chunk output, 4x4 register tiles, k-major smem.
//   A = mask(pq @ pk^T);  out = (A@v + pq@S_prefix) / (rowsum(A)+pq.s_prefix)
// ---------------------------------------------------------------------------
__global__ void attn_out_kernel(float* __restrict__ out) {
    extern __shared__ float sm[];
    float* pqT = sm;                  // [d][i]  64*68
    float* pkT = pqT + 64 * 68;       // [d][j]  64*68
    float* AsT = pkT + 64 * 68;       // [j][i]  64*68
    float* vs  = AsT + 64 * 68;       // [t][dv] 64*68
    float* Ss  = vs  + 64 * 68;       // [d][dv] 64*68
    float* ssm = Ss  + 64 * 68;       // 64
    float* dinv= ssm + 64;            // 64

    const int tid = threadIdx.x;
    const int cc = blockIdx.x;
    const int nh = blockIdx.y;

    const float* qbase = g_q + (nh * L + cc * C) * D;
    const float* kbase = g_k + (nh * L + cc * C) * D;
    const float* vbase = g_v + (nh * L + cc * C) * D;
    const float* pbase = g_prefix + (nh * NC + cc) * STSZ;

    #pragma unroll
    for (int i = 0; i < 4; i++) {
        int q4 = tid + i * 256;
        int r = q4 >> 4;
        int c4 = (q4 & 15) * 4;
        float4 qv = *(const float4*)&qbase[r * D + c4];
        pqT[(c4 + 0) * 68 + r] = qv.x; pqT[(c4 + 1) * 68 + r] = qv.y;
        pqT[(c4 + 2) * 68 + r] = qv.z; pqT[(c4 + 3) * 68 + r] = qv.w;
        float4 kv = *(const float4*)&kbase[r * D + c4];
        pkT[(c4 + 0) * 68 + r] = kv.x; pkT[(c4 + 1) * 68 + r] = kv.y;
        pkT[(c4 + 2) * 68 + r] = kv.z; pkT[(c4 + 3) * 68 + r] = kv.w;
        *(float4*)&vs[r * 68 + c4] = *(const float4*)&vbase[r * D + c4];
        *(float4*)&Ss[r * 68 + c4] = *(const float4*)&pbase[r * D + c4];
    }
    if (tid < 64) ssm[tid] = pbase[D * D + tid];
    __syncthreads();

    const int i0 = (tid >> 4) * 4;
    const int j0 = (tid & 15) * 4;

    // Stage 1: A tile (4x4 per thread)
    float a[4][4];
    #pragma unroll
    for (int r = 0; r < 4; r++)
        #pragma unroll
        for (int c = 0; c < 4; c++) a[r][c] = 0.0f;

    #pragma unroll 8
    for (int d = 0; d < D; d++) {
        float4 qa = *(float4*)&pqT[d * 68 + i0];
        float4 kb = *(float4*)&pkT[d * 68 + j0];
        float am[4] = {qa.x, qa.y, qa.z, qa.w};
        float bn[4] = {kb.x, kb.y, kb.z, kb.w};
        #pragma unroll
        for (int r = 0; r < 4; r++)
            #pragma unroll
            for (int c = 0; c < 4; c++)
                a[r][c] += am[r] * bn[c];
    }
    #pragma unroll
    for (int r = 0; r < 4; r++)
        #pragma unroll
        for (int c = 0; c < 4; c++) {
            int i = i0 + r, j = j0 + c;
            AsT[j * 68 + i] = (j <= i) ? a[r][c] : 0.0f;
        }
    __syncthreads();

    // Denominator per row
    if (tid < 64) {
        float den = 0.0f;
        #pragma unroll 8
        for (int j = 0; j < C; j++) den += AsT[j * 68 + tid];
        #pragma unroll 8
        for (int d = 0; d < D; d++) den += pqT[d * 68 + tid] * ssm[d];
        dinv[tid] = 1.0f / den;
    }
    __syncthreads();

    // Stage 2: out tile = A@v + q@S  (4x4 per thread; dv block = j0)
    float o[4][4];
    #pragma unroll
    for (int r = 0; r < 4; r++)
        #pragma unroll
        for (int c = 0; c < 4; c++) o[r][c] = 0.0f;

    #pragma unroll 8
    for (int j = 0; j < C; j++) {
        float4 aa = *(float4*)&AsT[j * 68 + i0];
        float4 vv = *(float4*)&vs[j * 68 + j0];
        float am[4] = {aa.x, aa.y, aa.z, aa.w};
        float bn[4] = {vv.x, vv.y, vv.z, vv.w};
        #pragma unroll
        for (int r = 0; r < 4; r++)
            #pragma unroll
            for (int c = 0; c < 4; c++)
                o[r][c] += am[r] * bn[c];
    }
    #pragma unroll 8
    for (int d = 0; d < D; d++) {
        float4 qa = *(float4*)&pqT[d * 68 + i0];
        float4 sv = *(float4*)&Ss[d * 68 + j0];
        float am[4] = {qa.x, qa.y, qa.z, qa.w};
        float bn[4] = {sv.x, sv.y, sv.z, sv.w};
        #pragma unroll
        for (int r = 0; r < 4; r++)
            #pragma unroll
            for (int c = 0; c < 4; c++)
                o[r][c] += am[r] * bn[c];
    }

    const int n = nh >> 3;
    const int h = nh & 7;
    #pragma unroll
    for (int r = 0; r < 4; r++) {
        int i = i0 + r;
        float inv = dinv[i];
        int l = cc * C + i;
        float4 ov;
        ov.x = o[r][0] * inv; ov.y = o[r][1] * inv;
        ov.z = o[r][2] * inv; ov.w = o[r][3] * inv;
        *(float4*)&out[(n * L + l) * DIM + h * D + j0] = ov;
    }
}

// ---------------------------------------------------------------------------
extern "C" void kernel_launch(void* const* d_in, const int* in_sizes, int n_in,
                              void* d_out, int out_size) {
    const float* query   = (const float*)d_in[0];
    const float* key_seq = (const float*)d_in[1];
    const float* Wq      = (const float*)d_in[2];
    const float* Wk      = (const float*)d_in[3];
    const float* Wv      = (const float*)d_in[4];
    float* out = (float*)d_out;

    float *gq, *gk, *gv;
    cudaGetSymbolAddress((void**)&gq, g_q);
    cudaGetSymbolAddress((void**)&gk, g_k);
    cudaGetSymbolAddress((void**)&gv, g_v);

    const int SMEM_ATTN = (5 * 64 * 68 + 128) * 4;   // 87552 B
    cudaFuncSetAttribute(attn_out_kernel,
                         cudaFuncAttributeMaxDynamicSharedMemorySize, SMEM_ATTN);

    dim3 ggrid(DIM / 128, ROWS / 128);    // (4, 32)
    gemm_proj_tc<true ><<<ggrid, 256>>>(query,   Wq, gq);
    gemm_proj_tc<true ><<<ggrid, 256>>>(key_seq, Wk, gk);
    gemm_proj_tc<false><<<ggrid, 256>>>(key_seq, Wv, gv);

    chunk_state_kernel<<<dim3(NC, NH), 256>>>();
    scan_states_kernel<<<dim3(NH, (STSZ + 255) / 256), 256>>>();
    attn_out_kernel<<<dim3(NC, NH), 256, SMEM_ATTN>>>(out);
}

// round 4
// speedup vs baseline: 3.0605x; 1.1017x over previous
#include <cuda_runtime.h>
#include <math.h>
#include <stdint.h>

// Problem constants
#define NB    2
#define L     2048
#define DIM   512
#define H     8
#define D     64
#define NH    (NB*H)          // 16
#define ROWS  (NB*L)          // 4096
#define C     64              // chunk length
#define NC    (L/C)           // 32 chunks
#define STSZ  (D*D + D)       // 4160 floats per chunk state

// Scratch (device globals; allocation-free)
__device__ float g_q[NH * L * D];
__device__ float g_k[NH * L * D];
__device__ float g_v[NH * L * D];
__device__ float g_state[NH * NC * STSZ];
__device__ float g_prefix[NH * NC * STSZ];
__device__ float g_xr[2 * ROWS * DIM];     // tf32-rounded query | key_seq
__device__ float g_wr[3 * DIM * DIM];      // tf32-rounded Wq | Wk | Wv

__device__ __forceinline__ float softplus_f(float x) {
    return (x > 20.0f) ? x : log1pf(__expf(x));
}

__device__ __forceinline__ float tf32_round(float x) {
    unsigned u;
    asm("cvt.rna.tf32.f32 %0, %1;" : "=r"(u) : "f"(x));
    return __uint_as_float(u);
}

__device__ __forceinline__ void cp16(uint32_t dst, const float* src) {
    asm volatile("cp.async.cg.shared.global [%0], [%1], 16;" :: "r"(dst), "l"(src));
}
__device__ __forceinline__ void cp_commit() {
    asm volatile("cp.async.commit_group;");
}

// ---------------------------------------------------------------------------
// Kernel 0: pre-round inputs to nearest-tf32 (so GEMM needs no cvt in-loop;
// the mma's internal truncation of already-rounded values is exact).
// ---------------------------------------------------------------------------
__global__ void prep_kernel(const float* __restrict__ query,
                            const float* __restrict__ key_seq,
                            const float* __restrict__ Wq,
                            const float* __restrict__ Wk,
                            const float* __restrict__ Wv) {
    const int XQ4 = ROWS * DIM / 4;          // per-input float4 count
    const int W4  = DIM * DIM / 4;
    int idx = blockIdx.x * blockDim.x + threadIdx.x;  // 0 .. 2*XQ4+3*W4-1

    const float* src;
    float* dst;
    if (idx < 2 * XQ4) {
        src = (idx < XQ4) ? query : key_seq;
        dst = g_xr;
        // dst offset equals idx (query occupies first XQ4 slots)
        src += (idx < XQ4 ? idx : idx - XQ4) * 4 + (idx < XQ4 ? 0 : 0);
        src = (idx < XQ4) ? query + idx * 4 : key_seq + (idx - XQ4) * 4;
        dst += idx * 4;
    } else {
        int w = idx - 2 * XQ4;
        int wi = w / W4;
        const float* ws[3] = {Wq, Wk, Wv};
        src = ws[wi] + (w - wi * W4) * 4;
        dst = g_wr + w * 4;
    }
    float4 v = *(const float4*)src;
    v.x = tf32_round(v.x); v.y = tf32_round(v.y);
    v.z = tf32_round(v.z); v.w = tf32_round(v.w);
    *(float4*)dst = v;
}

// ---------------------------------------------------------------------------
// Kernel 1: merged tensor-core TF32 GEMM. z selects (X, W, out, softplus).
// Block tile 128x128, K-tile 32, 256 threads, warp tile 64x32.
// cp.async double-buffered row-major smem (pad 36 -> conflict-free fragment
// loads), one __syncthreads per K-tile.
// ---------------------------------------------------------------------------
#define XPAD 36
#define TILEF (128 * XPAD)          // floats per operand tile
#define STAGEF (2 * TILEF)          // X + W per stage
#define GEMM_SMEM (2 * STAGEF * 4)  // bytes (73728)

__global__ void __launch_bounds__(256, 2)
gemm_proj_tc(float* __restrict__ out_q,
             float* __restrict__ out_k,
             float* __restrict__ out_v) {
    extern __shared__ float sm[];

    const int tid  = threadIdx.x;
    const int lane = tid & 31;
    const int warp = tid >> 5;
    const int wm = warp >> 2;
    const int wn = warp & 3;
    const int g  = lane >> 2;
    const int tg = lane & 3;

    const int z = blockIdx.z;
    const int rowBase = blockIdx.y * 128;
    const int colBase = blockIdx.x * 128;

    const float* Xg = g_xr + (z == 0 ? 0 : ROWS * DIM) + rowBase * DIM;
    const float* Wg = g_wr + z * DIM * DIM + colBase * DIM;
    float* out = (z == 0) ? out_q : (z == 1) ? out_k : out_v;
    const bool do_sp = (z < 2);

    uint32_t smem_u32;
    asm("{ .reg .u64 t; cvta.to.shared.u64 t, %1; cvt.u32.u64 %0, t; }"
        : "=r"(smem_u32) : "l"(sm));

    // cp.async staging coords: r = tid>>1 (row 0..127), h = tid&1 (16-float half)
    const int cr = tid >> 1;
    const int ch = (tid & 1) * 16;

    // prologue: stage 0
    {
        uint32_t xd = smem_u32 + (cr * XPAD + ch) * 4;
        uint32_t wd = smem_u32 + (TILEF + cr * XPAD + ch) * 4;
        const float* xs = Xg + cr * DIM + ch;
        const float* ws = Wg + cr * DIM + ch;
        #pragma unroll
        for (int s = 0; s < 4; s++) {
            cp16(xd + s * 16, xs + s * 4);
            cp16(wd + s * 16, ws + s * 4);
        }
        cp_commit();
    }

    float acc[4][4][4];
    #pragma unroll
    for (int a = 0; a < 4; a++)
        #pragma unroll
        for (int b = 0; b < 4; b++)
            #pragma unroll
            for (int r = 0; r < 4; r++) acc[a][b][r] = 0.0f;

    const int NT = DIM / 32;   // 16 K-tiles
    for (int t = 0; t < NT; t++) {
        // issue next tile
        if (t + 1 < NT) {
            int so = ((t + 1) & 1) * STAGEF;
            uint32_t xd = smem_u32 + (so + cr * XPAD + ch) * 4;
            uint32_t wd = smem_u32 + (so + TILEF + cr * XPAD + ch) * 4;
            const float* xs = Xg + cr * DIM + (t + 1) * 32 + ch;
            const float* ws = Wg + cr * DIM + (t + 1) * 32 + ch;
            #pragma unroll
            for (int s = 0; s < 4; s++) {
                cp16(xd + s * 16, xs + s * 4);
                cp16(wd + s * 16, ws + s * 4);
            }
            cp_commit();
            asm volatile("cp.async.wait_group 1;");
        } else {
            asm volatile("cp.async.wait_group 0;");
        }
        __syncthreads();

        const float* Xs = sm + (t & 1) * STAGEF;
        const float* Ws = Xs + TILEF;

        #pragma unroll
        for (int kf = 0; kf < 4; kf++) {
            const int kc = kf * 8 + tg;
            unsigned afr[4][4], bfr[4][2];
            #pragma unroll
            for (int mf = 0; mf < 4; mf++) {
                const float* a = Xs + (wm * 64 + mf * 16 + g) * XPAD + kc;
                afr[mf][0] = __float_as_uint(a[0]);
                afr[mf][1] = __float_as_uint(a[8 * XPAD]);
                afr[mf][2] = __float_as_uint(a[4]);
                afr[mf][3] = __float_as_uint(a[8 * XPAD + 4]);
            }
            #pragma unroll
            for (int nf = 0; nf < 4; nf++) {
                const float* b = Ws + (wn * 32 + nf * 8 + g) * XPAD + kc;
                bfr[nf][0] = __float_as_uint(b[0]);
                bfr[nf][1] = __float_as_uint(b[4]);
            }
            #pragma unroll
            for (int mf = 0; mf < 4; mf++)
                #pragma unroll
                for (int nf = 0; nf < 4; nf++) {
                    asm volatile(
                        "mma.sync.aligned.m16n8k8.row.col.f32.tf32.tf32.f32 "
                        "{%0,%1,%2,%3}, {%4,%5,%6,%7}, {%8,%9}, {%0,%1,%2,%3};"
                        : "+f"(acc[mf][nf][0]), "+f"(acc[mf][nf][1]),
                          "+f"(acc[mf][nf][2]), "+f"(acc[mf][nf][3])
                        : "r"(afr[mf][0]), "r"(afr[mf][1]),
                          "r"(afr[mf][2]), "r"(afr[mf][3]),
                          "r"(bfr[nf][0]), "r"(bfr[nf][1]));
                }
        }
        __syncthreads();
    }

    // epilogue: optional softplus + scatter to [nh][l][d]
    #pragma unroll
    for (int mf = 0; mf < 4; mf++) {
        #pragma unroll
        for (int nf = 0; nf < 4; nf++) {
            int col = colBase + wn * 32 + nf * 8 + tg * 2;
            int h = col >> 6;
            int dd = col & 63;
            #pragma unroll
            for (int half = 0; half < 2; half++) {
                int row = rowBase + wm * 64 + mf * 16 + half * 8 + g;
                int n = row >> 11;
                int l = row & (L - 1);
                float v0 = acc[mf][nf][half * 2 + 0];
                float v1 = acc[mf][nf][half * 2 + 1];
                if (do_sp) { v0 = softplus_f(v0); v1 = softplus_f(v1); }
                float2 o; o.x = v0; o.y = v1;
                *(float2*)&out[((n * H + h) * L + l) * D + dd] = o;
            }
        }
    }
}

// ---------------------------------------------------------------------------
// Kernel 2: per-chunk state. 128 threads, 8x4 register tile.
// ---------------------------------------------------------------------------
__global__ void chunk_state_kernel() {
    __shared__ float pks[64][68];
    __shared__ float vs[64][68];

    const int tid = threadIdx.x;
    const int cc = blockIdx.x;
    const int nh = blockIdx.y;

    const float* kbase = g_k + (nh * L + cc * C) * D;
    const float* vbase = g_v + (nh * L + cc * C) * D;

    #pragma unroll
    for (int i = 0; i < 8; i++) {
        int q4 = tid + i * 128;
        int r = q4 >> 4;
        int c4 = (q4 & 15) * 4;
        *(float4*)&pks[r][c4] = *(const float4*)&kbase[r * D + c4];
        *(float4*)&vs[r][c4]  = *(const float4*)&vbase[r * D + c4];
    }
    __syncthreads();

    const int dk0 = (tid >> 4) * 8;
    const int dv0 = (tid & 15) * 4;
    float acc[8][4];
    #pragma unroll
    for (int r = 0; r < 8; r++)
        #pragma unroll
        for (int c = 0; c < 4; c++) acc[r][c] = 0.0f;

    #pragma unroll 4
    for (int t = 0; t < C; t++) {
        float4 a0 = *(float4*)&pks[t][dk0];
        float4 a1 = *(float4*)&pks[t][dk0 + 4];
        float4 b  = *(float4*)&vs[t][dv0];
        float am[8] = {a0.x, a0.y, a0.z, a0.w, a1.x, a1.y, a1.z, a1.w};
        float bn[4] = {b.x, b.y, b.z, b.w};
        #pragma unroll
        for (int r = 0; r < 8; r++)
            #pragma unroll
            for (int c = 0; c < 4; c++)
                acc[r][c] += am[r] * bn[c];
    }

    float* sbase = g_state + (nh * NC + cc) * STSZ;
    #pragma unroll
    for (int r = 0; r < 8; r++) {
        float4 o;
        o.x = acc[r][0]; o.y = acc[r][1]; o.z = acc[r][2]; o.w = acc[r][3];
        *(float4*)&sbase[(dk0 + r) * D + dv0] = o;
    }

    if (tid < 64) {
        float s = 0.0f;
        #pragma unroll 8
        for (int t = 0; t < C; t++) s += pks[t][tid];
        sbase[D * D + tid] = s;
    }
}

// ---------------------------------------------------------------------------
// Kernel 3: exclusive prefix scan over chunks.
// ---------------------------------------------------------------------------
__global__ void scan_states_kernel() {
    const int nh = blockIdx.x;
    const int idx = blockIdx.y * 256 + threadIdx.x;
    if (idx >= STSZ) return;
    float run = 0.0f;
    int base = nh * NC * STSZ + idx;
    #pragma unroll 4
    for (int cc = 0; cc < NC; cc++) {
        g_prefix[base] = run;
        run += g_state[base];
        base += STSZ;
    }
}

// ---------------------------------------------------------------------------
// Kernel 4: per-chunk output (unchanged from R3).
// ---------------------------------------------------------------------------
__global__ void attn_out_kernel(float* __restrict__ out) {
    extern __shared__ float sm[];
    float* pqT = sm;
    float* pkT = pqT + 64 * 68;
    float* AsT = pkT + 64 * 68;
    float* vs  = AsT + 64 * 68;
    float* Ss  = vs  + 64 * 68;
    float* ssm = Ss  + 64 * 68;
    float* dinv= ssm + 64;

    const int tid = threadIdx.x;
    const int cc = blockIdx.x;
    const int nh = blockIdx.y;

    const float* qbase = g_q + (nh * L + cc * C) * D;
    const float* kbase = g_k + (nh * L + cc * C) * D;
    const float* vbase = g_v + (nh * L + cc * C) * D;
    const float* pbase = g_prefix + (nh * NC + cc) * STSZ;

    #pragma unroll
    for (int i = 0; i < 4; i++) {
        int q4 = tid + i * 256;
        int r = q4 >> 4;
        int c4 = (q4 & 15) * 4;
        float4 qv = *(const float4*)&qbase[r * D + c4];
        pqT[(c4 + 0) * 68 + r] = qv.x; pqT[(c4 + 1) * 68 + r] = qv.y;
        pqT[(c4 + 2) * 68 + r] = qv.z; pqT[(c4 + 3) * 68 + r] = qv.w;
        float4 kv = *(const float4*)&kbase[r * D + c4];
        pkT[(c4 + 0) * 68 + r] = kv.x; pkT[(c4 + 1) * 68 + r] = kv.y;
        pkT[(c4 + 2) * 68 + r] = kv.z; pkT[(c4 + 3) * 68 + r] = kv.w;
        *(float4*)&vs[r * 68 + c4] = *(const float4*)&vbase[r * D + c4];
        *(float4*)&Ss[r * 68 + c4] = *(const float4*)&pbase[r * D + c4];
    }
    if (tid < 64) ssm[tid] = pbase[D * D + tid];
    __syncthreads();

    const int i0 = (tid >> 4) * 4;
    const int j0 = (tid & 15) * 4;

    float a[4][4];
    #pragma unroll
    for (int r = 0; r < 4; r++)
        #pragma unroll
        for (int c = 0; c < 4; c++) a[r][c] = 0.0f;

    #pragma unroll 8
    for (int d = 0; d < D; d++) {
        float4 qa = *(float4*)&pqT[d * 68 + i0];
        float4 kb = *(float4*)&pkT[d * 68 + j0];
        float am[4] = {qa.x, qa.y, qa.z, qa.w};
        float bn[4] = {kb.x, kb.y, kb.z, kb.w};
        #pragma unroll
        for (int r = 0; r < 4; r++)
            #pragma unroll
            for (int c = 0; c < 4; c++)
                a[r][c] += am[r] * bn[c];
    }
    #pragma unroll
    for (int r = 0; r < 4; r++)
        #pragma unroll
        for (int c = 0; c < 4; c++) {
            int i = i0 + r, j = j0 + c;
            AsT[j * 68 + i] = (j <= i) ? a[r][c] : 0.0f;
        }
    __syncthreads();

    if (tid < 64) {
        float den = 0.0f;
        #pragma unroll 8
        for (int j = 0; j < C; j++) den += AsT[j * 68 + tid];
        #pragma unroll 8
        for (int d = 0; d < D; d++) den += pqT[d * 68 + tid] * ssm[d];
        dinv[tid] = 1.0f / den;
    }
    __syncthreads();

    float o[4][4];
    #pragma unroll
    for (int r = 0; r < 4; r++)
        #pragma unroll
        for (int c = 0; c < 4; c++) o[r][c] = 0.0f;

    #pragma unroll 8
    for (int j = 0; j < C; j++) {
        float4 aa = *(float4*)&AsT[j * 68 + i0];
        float4 vv = *(float4*)&vs[j * 68 + j0];
        float am[4] = {aa.x, aa.y, aa.z, aa.w};
        float bn[4] = {vv.x, vv.y, vv.z, vv.w};
        #pragma unroll
        for (int r = 0; r < 4; r++)
            #pragma unroll
            for (int c = 0; c < 4; c++)
                o[r][c] += am[r] * bn[c];
    }
    #pragma unroll 8
    for (int d = 0; d < D; d++) {
        float4 qa = *(float4*)&pqT[d * 68 + i0];
        float4 sv = *(float4*)&Ss[d * 68 + j0];
        float am[4] = {qa.x, qa.y, qa.z, qa.w};
        float bn[4] = {sv.x, sv.y, sv.z, sv.w};
        #pragma unroll
        for (int r = 0; r < 4; r++)
            #pragma unroll
            for (int c = 0; c < 4; c++)
                o[r][c] += am[r] * bn[c];
    }

    const int n = nh >> 3;
    const int h = nh & 7;
    #pragma unroll
    for (int r = 0; r < 4; r++) {
        int i = i0 + r;
        float inv = dinv[i];
        int l = cc * C + i;
        float4 ov;
        ov.x = o[r][0] * inv; ov.y = o[r][1] * inv;
        ov.z = o[r][2] * inv; ov.w = o[r][3] * inv;
        *(float4*)&out[(n * L + l) * DIM + h * D + j0] = ov;
    }
}

// ---------------------------------------------------------------------------
extern "C" void kernel_launch(void* const* d_in, const int* in_sizes, int n_in,
                              void* d_out, int out_size) {
    const float* query   = (const float*)d_in[0];
    const float* key_seq = (const float*)d_in[1];
    const float* Wq      = (const float*)d_in[2];
    const float* Wk      = (const float*)d_in[3];
    const float* Wv      = (const float*)d_in[4];
    float* out = (float*)d_out;

    float *gq, *gk, *gv;
    cudaGetSymbolAddress((void**)&gq, g_q);
    cudaGetSymbolAddress((void**)&gk, g_k);
    cudaGetSymbolAddress((void**)&gv, g_v);

    const int SMEM_ATTN = (5 * 64 * 68 + 128) * 4;
    cudaFuncSetAttribute(attn_out_kernel,
                         cudaFuncAttributeMaxDynamicSharedMemorySize, SMEM_ATTN);
    cudaFuncSetAttribute(gemm_proj_tc,
                         cudaFuncAttributeMaxDynamicSharedMemorySize, GEMM_SMEM);

    // prep: round inputs to tf32 grid
    const int total4 = (2 * ROWS * DIM + 3 * DIM * DIM) / 4;
    prep_kernel<<<total4 / 256, 256>>>(query, key_seq, Wq, Wk, Wv);

    dim3 ggrid(DIM / 128, ROWS / 128, 3);   // (4, 32, 3) = 384 CTAs
    gemm_proj_tc<<<ggrid, 256, GEMM_SMEM>>>(gq, gk, gv);

    chunk_state_kernel<<<dim3(NC, NH), 128>>>();
    scan_states_kernel<<<dim3(NH, (STSZ + 255) / 256), 256>>>();
    attn_out_kernel<<<dim3(NC, NH), 256, SMEM_ATTN>>>(out);
}

// round 6
// speedup vs baseline: 3.4574x; 1.1297x over previous
#include <cuda_runtime.h>
#include <math.h>
#include <stdint.h>

// Problem constants
#define NB    2
#define L     2048
#define DIM   512
#define H     8
#define D     64
#define NH    (NB*H)          // 16
#define ROWS  (NB*L)          // 4096
#define C     64              // chunk length
#define NC    (L/C)           // 32 chunks
#define STSZ  (D*D + D)       // 4160 floats per chunk state

// Scratch (device globals; allocation-free)
__device__ float g_q[NH * L * D];
__device__ float g_k[NH * L * D];
__device__ float g_v[NH * L * D];
__device__ float g_state[NH * NC * STSZ];
__device__ float g_prefix[NH * NC * STSZ];
__device__ float g_xr[2 * ROWS * DIM];     // tf32-rounded query | key_seq
__device__ float g_wr[3 * DIM * DIM];      // tf32-rounded Wq | Wk | Wv

__device__ __forceinline__ float softplus_f(float x) {
    return (x > 20.0f) ? x : log1pf(__expf(x));
}

__device__ __forceinline__ float tf32_round(float x) {
    unsigned u;
    asm("cvt.rna.tf32.f32 %0, %1;" : "=r"(u) : "f"(x));
    return __uint_as_float(u);
}

__device__ __forceinline__ void cp16(uint32_t dst, const float* src) {
    asm volatile("cp.async.cg.shared.global [%0], [%1], 16;" :: "r"(dst), "l"(src));
}
__device__ __forceinline__ void cp_commit() {
    asm volatile("cp.async.commit_group;");
}

#define MMA_TF32(ACC, A0, A1, A2, A3, B0, B1)                                  \
    asm volatile(                                                              \
        "mma.sync.aligned.m16n8k8.row.col.f32.tf32.tf32.f32 "                 \
        "{%0,%1,%2,%3}, {%4,%5,%6,%7}, {%8,%9}, {%0,%1,%2,%3};"               \
        : "+f"((ACC)[0]), "+f"((ACC)[1]), "+f"((ACC)[2]), "+f"((ACC)[3])       \
        : "r"(A0), "r"(A1), "r"(A2), "r"(A3), "r"(B0), "r"(B1))

// ---------------------------------------------------------------------------
// Kernel 0: pre-round inputs to nearest-tf32.
// ---------------------------------------------------------------------------
__global__ void prep_kernel(const float* __restrict__ query,
                            const float* __restrict__ key_seq,
                            const float* __restrict__ Wq,
                            const float* __restrict__ Wk,
                            const float* __restrict__ Wv) {
    const int XQ4 = ROWS * DIM / 4;
    const int W4  = DIM * DIM / 4;
    int idx = blockIdx.x * blockDim.x + threadIdx.x;

    const float* src;
    float* dst;
    if (idx < 2 * XQ4) {
        src = (idx < XQ4) ? query + idx * 4 : key_seq + (idx - XQ4) * 4;
        dst = g_xr + idx * 4;
    } else {
        int w = idx - 2 * XQ4;
        int wi = w / W4;
        const float* ws[3] = {Wq, Wk, Wv};
        src = ws[wi] + (w - wi * W4) * 4;
        dst = g_wr + w * 4;
    }
    float4 v = *(const float4*)src;
    v.x = tf32_round(v.x); v.y = tf32_round(v.y);
    v.z = tf32_round(v.z); v.w = tf32_round(v.w);
    *(float4*)dst = v;
}

// ---------------------------------------------------------------------------
// Kernel 1: merged TF32 GEMM (unchanged from R4).
// ---------------------------------------------------------------------------
#define XPAD 36
#define TILEF (128 * XPAD)
#define STAGEF (2 * TILEF)
#define GEMM_SMEM (2 * STAGEF * 4)

__global__ void __launch_bounds__(256, 2)
gemm_proj_tc(float* __restrict__ out_q,
             float* __restrict__ out_k,
             float* __restrict__ out_v) {
    extern __shared__ float sm[];

    const int tid  = threadIdx.x;
    const int lane = tid & 31;
    const int warp = tid >> 5;
    const int wm = warp >> 2;
    const int wn = warp & 3;
    const int g  = lane >> 2;
    const int tg = lane & 3;

    const int z = blockIdx.z;
    const int rowBase = blockIdx.y * 128;
    const int colBase = blockIdx.x * 128;

    const float* Xg = g_xr + (z == 0 ? 0 : ROWS * DIM) + rowBase * DIM;
    const float* Wg = g_wr + z * DIM * DIM + colBase * DIM;
    float* out = (z == 0) ? out_q : (z == 1) ? out_k : out_v;
    const bool do_sp = (z < 2);

    uint32_t smem_u32;
    asm("{ .reg .u64 t; cvta.to.shared.u64 t, %1; cvt.u32.u64 %0, t; }"
        : "=r"(smem_u32) : "l"(sm));

    const int cr = tid >> 1;
    const int ch = (tid & 1) * 16;

    {
        uint32_t xd = smem_u32 + (cr * XPAD + ch) * 4;
        uint32_t wd = smem_u32 + (TILEF + cr * XPAD + ch) * 4;
        const float* xs = Xg + cr * DIM + ch;
        const float* ws = Wg + cr * DIM + ch;
        #pragma unroll
        for (int s = 0; s < 4; s++) {
            cp16(xd + s * 16, xs + s * 4);
            cp16(wd + s * 16, ws + s * 4);
        }
        cp_commit();
    }

    float acc[4][4][4];
    #pragma unroll
    for (int a = 0; a < 4; a++)
        #pragma unroll
        for (int b = 0; b < 4; b++)
            #pragma unroll
            for (int r = 0; r < 4; r++) acc[a][b][r] = 0.0f;

    const int NT = DIM / 32;
    for (int t = 0; t < NT; t++) {
        if (t + 1 < NT) {
            int so = ((t + 1) & 1) * STAGEF;
            uint32_t xd = smem_u32 + (so + cr * XPAD + ch) * 4;
            uint32_t wd = smem_u32 + (so + TILEF + cr * XPAD + ch) * 4;
            const float* xs = Xg + cr * DIM + (t + 1) * 32 + ch;
            const float* ws = Wg + cr * DIM + (t + 1) * 32 + ch;
            #pragma unroll
            for (int s = 0; s < 4; s++) {
                cp16(xd + s * 16, xs + s * 4);
                cp16(wd + s * 16, ws + s * 4);
            }
            cp_commit();
            asm volatile("cp.async.wait_group 1;");
        } else {
            asm volatile("cp.async.wait_group 0;");
        }
        __syncthreads();

        const float* Xs = sm + (t & 1) * STAGEF;
        const float* Ws = Xs + TILEF;

        #pragma unroll
        for (int kf = 0; kf < 4; kf++) {
            const int kc = kf * 8 + tg;
            unsigned afr[4][4], bfr[4][2];
            #pragma unroll
            for (int mf = 0; mf < 4; mf++) {
                const float* a = Xs + (wm * 64 + mf * 16 + g) * XPAD + kc;
                afr[mf][0] = __float_as_uint(a[0]);
                afr[mf][1] = __float_as_uint(a[8 * XPAD]);
                afr[mf][2] = __float_as_uint(a[4]);
                afr[mf][3] = __float_as_uint(a[8 * XPAD + 4]);
            }
            #pragma unroll
            for (int nf = 0; nf < 4; nf++) {
                const float* b = Ws + (wn * 32 + nf * 8 + g) * XPAD + kc;
                bfr[nf][0] = __float_as_uint(b[0]);
                bfr[nf][1] = __float_as_uint(b[4]);
            }
            #pragma unroll
            for (int mf = 0; mf < 4; mf++)
                #pragma unroll
                for (int nf = 0; nf < 4; nf++)
                    MMA_TF32(acc[mf][nf], afr[mf][0], afr[mf][1], afr[mf][2],
                             afr[mf][3], bfr[nf][0], bfr[nf][1]);
        }
        __syncthreads();
    }

    #pragma unroll
    for (int mf = 0; mf < 4; mf++) {
        #pragma unroll
        for (int nf = 0; nf < 4; nf++) {
            int col = colBase + wn * 32 + nf * 8 + tg * 2;
            int h = col >> 6;
            int dd = col & 63;
            #pragma unroll
            for (int half = 0; half < 2; half++) {
                int row = rowBase + wm * 64 + mf * 16 + half * 8 + g;
                int n = row >> 11;
                int l = row & (L - 1);
                float v0 = acc[mf][nf][half * 2 + 0];
                float v1 = acc[mf][nf][half * 2 + 1];
                if (do_sp) { v0 = softplus_f(v0); v1 = softplus_f(v1); }
                float2 o; o.x = v0; o.y = v1;
                *(float2*)&out[((n * H + h) * L + l) * D + dd] = o;
            }
        }
    }
}

// ---------------------------------------------------------------------------
// Kernel 2: per-chunk state via tensor cores. S = pk^T @ v, s = colsum(pk).
// 128 threads (4 warps), each warp a 16-row slab of the 64x64 output.
// ---------------------------------------------------------------------------
#define AP 68

__global__ void __launch_bounds__(128, 2) chunk_state_tc() {
    __shared__ float pkT[64][AP];   // [dk][t]  (tf32)
    __shared__ float vT[64][AP];    // [dv][t]  (tf32)

    const int tid = threadIdx.x;
    const int lane = tid & 31;
    const int warp = tid >> 5;
    const int g = lane >> 2;
    const int tg = lane & 3;
    const int cc = blockIdx.x;
    const int nh = blockIdx.y;

    const float* kbase = g_k + (nh * L + cc * C) * D;
    const float* vbase = g_v + (nh * L + cc * C) * D;

    // staging with transpose + tf32 rounding
    const int r = tid >> 1;
    const int c0 = (tid & 1) * 32;
    #pragma unroll
    for (int i = 0; i < 8; i++) {
        int c = c0 + i * 4;
        float4 kv = *(const float4*)&kbase[r * D + c];
        pkT[c + 0][r] = tf32_round(kv.x); pkT[c + 1][r] = tf32_round(kv.y);
        pkT[c + 2][r] = tf32_round(kv.z); pkT[c + 3][r] = tf32_round(kv.w);
        float4 vv = *(const float4*)&vbase[r * D + c];
        vT[c + 0][r] = tf32_round(vv.x); vT[c + 1][r] = tf32_round(vv.y);
        vT[c + 2][r] = tf32_round(vv.z); vT[c + 3][r] = tf32_round(vv.w);
    }
    __syncthreads();

    const int rbase = warp * 16;
    float acc[8][4];
    #pragma unroll
    for (int nf = 0; nf < 8; nf++)
        #pragma unroll
        for (int q = 0; q < 4; q++) acc[nf][q] = 0.0f;

    #pragma unroll
    for (int kf = 0; kf < 8; kf++) {
        const int kc = kf * 8 + tg;
        const float* ap = &pkT[rbase + g][kc];
        unsigned a0 = __float_as_uint(ap[0]);
        unsigned a1 = __float_as_uint(ap[8 * AP]);
        unsigned a2 = __float_as_uint(ap[4]);
        unsigned a3 = __float_as_uint(ap[8 * AP + 4]);
        #pragma unroll
        for (int nf = 0; nf < 8; nf++) {
            const float* bp = &vT[nf * 8 + g][kc];
            unsigned b0 = __float_as_uint(bp[0]);
            unsigned b1 = __float_as_uint(bp[4]);
            MMA_TF32(acc[nf], a0, a1, a2, a3, b0, b1);
        }
    }

    float* sbase = g_state + (nh * NC + cc) * STSZ;
    #pragma unroll
    for (int nf = 0; nf < 8; nf++) {
        int dv = nf * 8 + tg * 2;
        #pragma unroll
        for (int half = 0; half < 2; half++) {
            int dk = rbase + half * 8 + g;
            float2 o; o.x = acc[nf][half * 2]; o.y = acc[nf][half * 2 + 1];
            *(float2*)&sbase[dk * D + dv] = o;
        }
    }

    if (tid < 64) {
        float s = 0.0f;
        #pragma unroll 16
        for (int t = 0; t < C; t++) s += pkT[tid][t];
        sbase[D * D + tid] = s;
    }
}

// ---------------------------------------------------------------------------
// Kernel 3: exclusive prefix scan, loads batched for MLP.
// ---------------------------------------------------------------------------
__global__ void scan_states_kernel() {
    const int nh = blockIdx.x;
    const int idx = blockIdx.y * 256 + threadIdx.x;
    if (idx >= STSZ) return;
    const int base = nh * NC * STSZ + idx;
    float vals[NC];
    #pragma unroll
    for (int cc = 0; cc < NC; cc++)
        vals[cc] = g_state[base + cc * STSZ];
    float run = 0.0f;
    #pragma unroll
    for (int cc = 0; cc < NC; cc++) {
        g_prefix[base + cc * STSZ] = run;
        run += vals[cc];
    }
}

// ---------------------------------------------------------------------------
// Kernel 4: per-chunk output via tensor cores.
// Stage1: A = mask(q @ k^T) -> rowsums + Af (tf32).  Stage2: A@v + q@S.
// 128 threads (4 warps), warp owns a 16-row slab.
// ---------------------------------------------------------------------------
#define SMEM_ATTN2 ((5 * 64 * AP + 3 * 64) * 4)

__global__ void __launch_bounds__(128, 2) attn_out_tc(float* __restrict__ out) {
    extern __shared__ float sm[];
    float* Qf = sm;                 // [i][d]   tf32
    float* Kf = Qf + 64 * AP;       // [j][d]   tf32
    float* VT = Kf + 64 * AP;       // [dv][j]  tf32
    float* ST = VT + 64 * AP;       // [dv][d]  tf32
    float* Af = ST + 64 * AP;       // [i][j]   tf32 (masked A)
    float* rs  = Af + 64 * AP;      // 64 rowsums
    float* ssm = rs + 64;           // 64
    float* dinv= ssm + 64;          // 64

    const int tid = threadIdx.x;
    const int lane = tid & 31;
    const int warp = tid >> 5;
    const int g = lane >> 2;
    const int tg = lane & 3;
    const int cc = blockIdx.x;
    const int nh = blockIdx.y;

    const float* qbase = g_q + (nh * L + cc * C) * D;
    const float* kbase = g_k + (nh * L + cc * C) * D;
    const float* vbase = g_v + (nh * L + cc * C) * D;
    const float* pbase = g_prefix + (nh * NC + cc) * STSZ;

    // staging
    const int r = tid >> 1;
    const int c0 = (tid & 1) * 32;
    #pragma unroll
    for (int i = 0; i < 8; i++) {
        int c = c0 + i * 4;
        float4 qv = *(const float4*)&qbase[r * D + c];
        qv.x = tf32_round(qv.x); qv.y = tf32_round(qv.y);
        qv.z = tf32_round(qv.z); qv.w = tf32_round(qv.w);
        *(float4*)&Qf[r * AP + c] = qv;
        float4 kv = *(const float4*)&kbase[r * D + c];
        kv.x = tf32_round(kv.x); kv.y = tf32_round(kv.y);
        kv.z = tf32_round(kv.z); kv.w = tf32_round(kv.w);
        *(float4*)&Kf[r * AP + c] = kv;
        float4 vv = *(const float4*)&vbase[r * D + c];
        VT[(c + 0) * AP + r] = tf32_round(vv.x);
        VT[(c + 1) * AP + r] = tf32_round(vv.y);
        VT[(c + 2) * AP + r] = tf32_round(vv.z);
        VT[(c + 3) * AP + r] = tf32_round(vv.w);
        float4 sv = *(const float4*)&pbase[r * D + c];
        ST[(c + 0) * AP + r] = tf32_round(sv.x);
        ST[(c + 1) * AP + r] = tf32_round(sv.y);
        ST[(c + 2) * AP + r] = tf32_round(sv.z);
        ST[(c + 3) * AP + r] = tf32_round(sv.w);
    }
    if (tid < 64) ssm[tid] = pbase[D * D + tid];
    __syncthreads();

    const int rbase = warp * 16;
    float acc[8][4];

    // ---- Stage 1: A = q @ k^T ----
    #pragma unroll
    for (int nf = 0; nf < 8; nf++)
        #pragma unroll
        for (int q = 0; q < 4; q++) acc[nf][q] = 0.0f;

    #pragma unroll
    for (int kf = 0; kf < 8; kf++) {
        const int kc = kf * 8 + tg;
        const float* ap = Qf + (rbase + g) * AP + kc;
        unsigned a0 = __float_as_uint(ap[0]);
        unsigned a1 = __float_as_uint(ap[8 * AP]);
        unsigned a2 = __float_as_uint(ap[4]);
        unsigned a3 = __float_as_uint(ap[8 * AP + 4]);
        #pragma unroll
        for (int nf = 0; nf < 8; nf++) {
            const float* bp = Kf + (nf * 8 + g) * AP + kc;
            unsigned b0 = __float_as_uint(bp[0]);
            unsigned b1 = __float_as_uint(bp[4]);
            MMA_TF32(acc[nf], a0, a1, a2, a3, b0, b1);
        }
    }

    // mask + rowsum + write Af (tf32)
    float rsum0 = 0.0f, rsum1 = 0.0f;
    const int row0 = rbase + g;
    const int row1 = rbase + 8 + g;
    #pragma unroll
    for (int nf = 0; nf < 8; nf++) {
        int col = nf * 8 + tg * 2;
        float x0 = (col     <= row0) ? acc[nf][0] : 0.0f;
        float x1 = (col + 1 <= row0) ? acc[nf][1] : 0.0f;
        rsum0 += x0 + x1;
        float2 p0; p0.x = tf32_round(x0); p0.y = tf32_round(x1);
        *(float2*)&Af[row0 * AP + col] = p0;
        float x2 = (col     <= row1) ? acc[nf][2] : 0.0f;
        float x3 = (col + 1 <= row1) ? acc[nf][3] : 0.0f;
        rsum1 += x2 + x3;
        float2 p1; p1.x = tf32_round(x2); p1.y = tf32_round(x3);
        *(float2*)&Af[row1 * AP + col] = p1;
    }
    rsum0 += __shfl_xor_sync(0xffffffffu, rsum0, 1);
    rsum0 += __shfl_xor_sync(0xffffffffu, rsum0, 2);
    rsum1 += __shfl_xor_sync(0xffffffffu, rsum1, 1);
    rsum1 += __shfl_xor_sync(0xffffffffu, rsum1, 2);
    if (tg == 0) { rs[row0] = rsum0; rs[row1] = rsum1; }
    __syncthreads();

    // denominator
    if (tid < 64) {
        float den = rs[tid];
        #pragma unroll 16
        for (int d = 0; d < D; d++) den += Qf[tid * AP + d] * ssm[d];
        dinv[tid] = 1.0f / den;
    }
    __syncthreads();

    // ---- Stage 2: out = A@v + q@S ----
    #pragma unroll
    for (int nf = 0; nf < 8; nf++)
        #pragma unroll
        for (int q = 0; q < 4; q++) acc[nf][q] = 0.0f;

    #pragma unroll
    for (int kf = 0; kf < 8; kf++) {
        const int kc = kf * 8 + tg;
        const float* ap = Af + (rbase + g) * AP + kc;
        unsigned a0 = __float_as_uint(ap[0]);
        unsigned a1 = __float_as_uint(ap[8 * AP]);
        unsigned a2 = __float_as_uint(ap[4]);
        unsigned a3 = __float_as_uint(ap[8 * AP + 4]);
        #pragma unroll
        for (int nf = 0; nf < 8; nf++) {
            const float* bp = VT + (nf * 8 + g) * AP + kc;
            unsigned b0 = __float_as_uint(bp[0]);
            unsigned b1 = __float_as_uint(bp[4]);
            MMA_TF32(acc[nf], a0, a1, a2, a3, b0, b1);
        }
    }
    #pragma unroll
    for (int kf = 0; kf < 8; kf++) {
        const int kc = kf * 8 + tg;
        const float* ap = Qf + (rbase + g) * AP + kc;
        unsigned a0 = __float_as_uint(ap[0]);
        unsigned a1 = __float_as_uint(ap[8 * AP]);
        unsigned a2 = __float_as_uint(ap[4]);
        unsigned a3 = __float_as_uint(ap[8 * AP + 4]);
        #pragma unroll
        for (int nf = 0; nf < 8; nf++) {
            const float* bp = ST + (nf * 8 + g) * AP + kc;
            unsigned b0 = __float_as_uint(bp[0]);
            unsigned b1 = __float_as_uint(bp[4]);
            MMA_TF32(acc[nf], a0, a1, a2, a3, b0, b1);
        }
    }

    // epilogue
    const int n = nh >> 3;
    const int h = nh & 7;
    #pragma unroll
    for (int nf = 0; nf < 8; nf++) {
        int dv = nf * 8 + tg * 2;
        #pragma unroll
        for (int half = 0; half < 2; half++) {
            int i = rbase + half * 8 + g;
            float inv = dinv[i];
            int l = cc * C + i;
            float2 ov;
            ov.x = acc[nf][half * 2 + 0] * inv;
            ov.y = acc[nf][half * 2 + 1] * inv;
            *(float2*)&out[(n * L + l) * DIM + h * D + dv] = ov;
        }
    }
}

// ---------------------------------------------------------------------------
extern "C" void kernel_launch(void* const* d_in, const int* in_sizes, int n_in,
                              void* d_out, int out_size) {
    const float* query   = (const float*)d_in[0];
    const float* key_seq = (const float*)d_in[1];
    const float* Wq      = (const float*)d_in[2];
    const float* Wk      = (const float*)d_in[3];
    const float* Wv      = (const float*)d_in[4];
    float* out = (float*)d_out;

    float *gq, *gk, *gv;
    cudaGetSymbolAddress((void**)&gq, g_q);
    cudaGetSymbolAddress((void**)&gk, g_k);
    cudaGetSymbolAddress((void**)&gv, g_v);

    cudaFuncSetAttribute(gemm_proj_tc,
                         cudaFuncAttributeMaxDynamicSharedMemorySize, GEMM_SMEM);
    cudaFuncSetAttribute(attn_out_tc,
                         cudaFuncAttributeMaxDynamicSharedMemorySize, SMEM_ATTN2);

    const int total4 = (2 * ROWS * DIM + 3 * DIM * DIM) / 4;
    prep_kernel<<<total4 / 256, 256>>>(query, key_seq, Wq, Wk, Wv);

    dim3 ggrid(DIM / 128, ROWS / 128, 3);
    gemm_proj_tc<<<ggrid, 256, GEMM_SMEM>>>(gq, gk, gv);

    chunk_state_tc<<<dim3(NC, NH), 128>>>();
    scan_states_kernel<<<dim3(NH, (STSZ + 255) / 256), 256>>>();
    attn_out_tc<<<dim3(NC, NH), 128, SMEM_ATTN2>>>(out);
}